// round 1
// baseline (speedup 1.0000x reference)
#include <cuda_runtime.h>
#include <cuda_bf16.h>

#define T_TOK   8192
#define HID     1024
#define FFN_DIM 4096
#define NEXP    8
#define TOTAL   (2 * T_TOK)

#define BM 128
#define BN 128
#define BK 16
#define NTHREADS 256

// ---------------- scratch (device globals: no cudaMalloc allowed) ----------------
__device__ int   g_counts[NEXP];
__device__ int   g_offsets[NEXP];
__device__ int   g_writePos[NEXP];
__device__ int   g_top2[T_TOK * 2];
__device__ int   g_entries[TOTAL];                    // token*2 + slot
__device__ float g_h1[(size_t)TOTAL * FFN_DIM];       // 268 MB intermediate
__device__ float g_partial[2][T_TOK][HID];            // slot-split partials (no atomics)

// ---------------- routing ----------------
__global__ void zero_counts_kernel() {
    if (threadIdx.x < NEXP) g_counts[threadIdx.x] = 0;
}

__global__ void gate_kernel(const float* __restrict__ x,
                            const float* __restrict__ gate_w,
                            const float* __restrict__ gate_b) {
    int warp = (blockIdx.x * blockDim.x + threadIdx.x) >> 5;
    int lane = threadIdx.x & 31;
    if (warp >= T_TOK) return;
    const float* xr = x + (size_t)warp * HID;
    float acc[NEXP];
#pragma unroll
    for (int e = 0; e < NEXP; e++) acc[e] = 0.f;
    for (int h = lane; h < HID; h += 32) {
        float xv = xr[h];
        const float* g = gate_w + h * NEXP;
#pragma unroll
        for (int e = 0; e < NEXP; e++) acc[e] += xv * g[e];
    }
#pragma unroll
    for (int e = 0; e < NEXP; e++)
#pragma unroll
        for (int o = 16; o > 0; o >>= 1)
            acc[e] += __shfl_down_sync(0xffffffffu, acc[e], o);
    if (lane == 0) {
        float v1 = -3.4e38f, v2 = -3.4e38f;
        int i1 = 0, i2 = 0;
#pragma unroll
        for (int e = 0; e < NEXP; e++) {
            float v = acc[e] + gate_b[e];
            if (v > v1) { v2 = v1; i2 = i1; v1 = v; i1 = e; }
            else if (v > v2) { v2 = v; i2 = e; }
        }
        g_top2[warp * 2 + 0] = i1;
        g_top2[warp * 2 + 1] = i2;
        atomicAdd(&g_counts[i1], 1);
        atomicAdd(&g_counts[i2], 1);
    }
}

__global__ void scan_kernel() {
    if (threadIdx.x == 0) {
        int off = 0;
        for (int e = 0; e < NEXP; e++) {
            g_offsets[e]  = off;
            g_writePos[e] = off;
            off += g_counts[e];
        }
    }
}

__global__ void fill_kernel() {
    int t = blockIdx.x * blockDim.x + threadIdx.x;
    if (t >= T_TOK) return;
    int e0 = g_top2[t * 2 + 0];
    int e1 = g_top2[t * 2 + 1];
    int p0 = atomicAdd(&g_writePos[e0], 1);
    g_entries[p0] = t * 2 + 0;
    int p1 = atomicAdd(&g_writePos[e1], 1);
    g_entries[p1] = t * 2 + 1;
}

// ---------------- GEMM1: h1 = relu(gather(x) @ w1[e] + b1[e]) ----------------
__global__ __launch_bounds__(NTHREADS, 2)
void gemm1_kernel(const float* __restrict__ x,
                  const float* __restrict__ w1,
                  const float* __restrict__ b1) {
    const int e  = blockIdx.z;
    const int mt = blockIdx.y;
    const int nt = blockIdx.x;
    const int count = g_counts[e];
    if (mt * BM >= count) return;
    const int base = g_offsets[e];

    __shared__ __align__(16) float As[BK][BM + 4];
    __shared__ __align__(16) float Bs[BK][BN];

    const int tid = threadIdx.x;
    const int ty = tid >> 4, tx = tid & 15;      // 16x16 threads, 8x8 micro-tile
    const int aRow0 = tid >> 2;                  // 0..63
    const int aCol  = (tid & 3) << 2;            // 0,4,8,12
    const int bRow0 = tid >> 5;                  // 0..7
    const int bCol  = (tid & 31) << 2;

    const float* Bmat = w1 + (size_t)e * HID * FFN_DIM;

    const float* aPtr[2];
#pragma unroll
    for (int p = 0; p < 2; p++) {
        int gi  = base + mt * BM + aRow0 + p * 64;
        int gci = min(gi, TOTAL - 1);
        int tok = (g_entries[gci] >> 1) & (T_TOK - 1);   // clamp garbage tail entries
        aPtr[p] = x + (size_t)tok * HID + aCol;
    }
    const float* bPtr = Bmat + (size_t)bRow0 * FFN_DIM + nt * BN + bCol;

    float acc[8][8];
#pragma unroll
    for (int i = 0; i < 8; i++)
#pragma unroll
        for (int j = 0; j < 8; j++) acc[i][j] = 0.f;

    float4 aReg[2], bReg[2];
    const int KT = HID / BK;  // 64
#pragma unroll
    for (int p = 0; p < 2; p++) aReg[p] = *(const float4*)(aPtr[p]);
#pragma unroll
    for (int p = 0; p < 2; p++) bReg[p] = *(const float4*)(bPtr + (size_t)(p * 8) * FFN_DIM);

    for (int kt = 0; kt < KT; kt++) {
#pragma unroll
        for (int p = 0; p < 2; p++) {
            int row = aRow0 + p * 64;
            As[aCol + 0][row] = aReg[p].x;
            As[aCol + 1][row] = aReg[p].y;
            As[aCol + 2][row] = aReg[p].z;
            As[aCol + 3][row] = aReg[p].w;
            *(float4*)&Bs[bRow0 + p * 8][bCol] = bReg[p];
        }
        __syncthreads();
        if (kt + 1 < KT) {
            int koff = (kt + 1) * BK;
#pragma unroll
            for (int p = 0; p < 2; p++) aReg[p] = *(const float4*)(aPtr[p] + koff);
#pragma unroll
            for (int p = 0; p < 2; p++)
                bReg[p] = *(const float4*)(bPtr + (size_t)(koff + p * 8) * FFN_DIM);
        }
#pragma unroll
        for (int k = 0; k < BK; k++) {
            float4 a0 = *(const float4*)&As[k][ty * 8];
            float4 a1 = *(const float4*)&As[k][ty * 8 + 4];
            float4 b0 = *(const float4*)&Bs[k][tx * 8];
            float4 b1v = *(const float4*)&Bs[k][tx * 8 + 4];
            float av[8] = {a0.x, a0.y, a0.z, a0.w, a1.x, a1.y, a1.z, a1.w};
            float bv[8] = {b0.x, b0.y, b0.z, b0.w, b1v.x, b1v.y, b1v.z, b1v.w};
#pragma unroll
            for (int i = 0; i < 8; i++)
#pragma unroll
                for (int j = 0; j < 8; j++) acc[i][j] += av[i] * bv[j];
        }
        __syncthreads();
    }

    float bias[8];
    const float* b1p = b1 + (size_t)e * FFN_DIM + nt * BN + tx * 8;
#pragma unroll
    for (int j = 0; j < 8; j++) bias[j] = b1p[j];

#pragma unroll
    for (int i = 0; i < 8; i++) {
        int row = ty * 8 + i;
        if (mt * BM + row < count) {
            int gi = base + mt * BM + row;
            float* dst = g_h1 + (size_t)gi * FFN_DIM + nt * BN + tx * 8;
            float4 v0, v1v;
            v0.x = fmaxf(acc[i][0] + bias[0], 0.f);
            v0.y = fmaxf(acc[i][1] + bias[1], 0.f);
            v0.z = fmaxf(acc[i][2] + bias[2], 0.f);
            v0.w = fmaxf(acc[i][3] + bias[3], 0.f);
            v1v.x = fmaxf(acc[i][4] + bias[4], 0.f);
            v1v.y = fmaxf(acc[i][5] + bias[5], 0.f);
            v1v.z = fmaxf(acc[i][6] + bias[6], 0.f);
            v1v.w = fmaxf(acc[i][7] + bias[7], 0.f);
            *(float4*)(dst)     = v0;
            *(float4*)(dst + 4) = v1v;
        }
    }
}

// ---------------- GEMM2: partial[slot][tok] = h1 @ w2[e] + b2[e] ----------------
__global__ __launch_bounds__(NTHREADS, 2)
void gemm2_kernel(const float* __restrict__ w2,
                  const float* __restrict__ b2) {
    const int e  = blockIdx.z;
    const int mt = blockIdx.y;
    const int nt = blockIdx.x;
    const int count = g_counts[e];
    if (mt * BM >= count) return;
    const int base = g_offsets[e];

    __shared__ __align__(16) float As[BK][BM + 4];
    __shared__ __align__(16) float Bs[BK][BN];

    const int tid = threadIdx.x;
    const int ty = tid >> 4, tx = tid & 15;
    const int aRow0 = tid >> 2;
    const int aCol  = (tid & 3) << 2;
    const int bRow0 = tid >> 5;
    const int bCol  = (tid & 31) << 2;

    const float* Bmat = w2 + (size_t)e * FFN_DIM * HID;

    const float* aPtr[2];
#pragma unroll
    for (int p = 0; p < 2; p++) {
        int gi  = base + mt * BM + aRow0 + p * 64;
        int gci = min(gi, TOTAL - 1);
        aPtr[p] = g_h1 + (size_t)gci * FFN_DIM + aCol;
    }
    const float* bPtr = Bmat + (size_t)bRow0 * HID + nt * BN + bCol;

    float acc[8][8];
#pragma unroll
    for (int i = 0; i < 8; i++)
#pragma unroll
        for (int j = 0; j < 8; j++) acc[i][j] = 0.f;

    float4 aReg[2], bReg[2];
    const int KT = FFN_DIM / BK;  // 256
#pragma unroll
    for (int p = 0; p < 2; p++) aReg[p] = *(const float4*)(aPtr[p]);
#pragma unroll
    for (int p = 0; p < 2; p++) bReg[p] = *(const float4*)(bPtr + (size_t)(p * 8) * HID);

    for (int kt = 0; kt < KT; kt++) {
#pragma unroll
        for (int p = 0; p < 2; p++) {
            int row = aRow0 + p * 64;
            As[aCol + 0][row] = aReg[p].x;
            As[aCol + 1][row] = aReg[p].y;
            As[aCol + 2][row] = aReg[p].z;
            As[aCol + 3][row] = aReg[p].w;
            *(float4*)&Bs[bRow0 + p * 8][bCol] = bReg[p];
        }
        __syncthreads();
        if (kt + 1 < KT) {
            int koff = (kt + 1) * BK;
#pragma unroll
            for (int p = 0; p < 2; p++) aReg[p] = *(const float4*)(aPtr[p] + koff);
#pragma unroll
            for (int p = 0; p < 2; p++)
                bReg[p] = *(const float4*)(bPtr + (size_t)(koff + p * 8) * HID);
        }
#pragma unroll
        for (int k = 0; k < BK; k++) {
            float4 a0 = *(const float4*)&As[k][ty * 8];
            float4 a1 = *(const float4*)&As[k][ty * 8 + 4];
            float4 b0 = *(const float4*)&Bs[k][tx * 8];
            float4 b1v = *(const float4*)&Bs[k][tx * 8 + 4];
            float av[8] = {a0.x, a0.y, a0.z, a0.w, a1.x, a1.y, a1.z, a1.w};
            float bv[8] = {b0.x, b0.y, b0.z, b0.w, b1v.x, b1v.y, b1v.z, b1v.w};
#pragma unroll
            for (int i = 0; i < 8; i++)
#pragma unroll
                for (int j = 0; j < 8; j++) acc[i][j] += av[i] * bv[j];
        }
        __syncthreads();
    }

    float bias[8];
    const float* b2p = b2 + (size_t)e * HID + nt * BN + tx * 8;
#pragma unroll
    for (int j = 0; j < 8; j++) bias[j] = b2p[j];

#pragma unroll
    for (int i = 0; i < 8; i++) {
        int row = ty * 8 + i;
        if (mt * BM + row < count) {
            int gi = base + mt * BM + row;
            int entry = g_entries[gi];
            int tok  = entry >> 1;
            int slot = entry & 1;
            float* dst = &g_partial[slot][tok][nt * BN + tx * 8];
            float4 v0, v1v;
            v0.x = acc[i][0] + bias[0];
            v0.y = acc[i][1] + bias[1];
            v0.z = acc[i][2] + bias[2];
            v0.w = acc[i][3] + bias[3];
            v1v.x = acc[i][4] + bias[4];
            v1v.y = acc[i][5] + bias[5];
            v1v.z = acc[i][6] + bias[6];
            v1v.w = acc[i][7] + bias[7];
            *(float4*)(dst)     = v0;
            *(float4*)(dst + 4) = v1v;
        }
    }
}

// ---------------- combine: out = partial0 + partial1 ----------------
__global__ void combine_kernel(float* __restrict__ out) {
    int i = blockIdx.x * blockDim.x + threadIdx.x;
    const int n4 = T_TOK * HID / 4;
    if (i < n4) {
        const float4* p0 = (const float4*)&g_partial[0][0][0];
        const float4* p1 = (const float4*)&g_partial[1][0][0];
        float4 a = p0[i], b = p1[i];
        float4 r;
        r.x = a.x + b.x; r.y = a.y + b.y; r.z = a.z + b.z; r.w = a.w + b.w;
        ((float4*)out)[i] = r;
    }
}

// ---------------- launch ----------------
extern "C" void kernel_launch(void* const* d_in, const int* in_sizes, int n_in,
                              void* d_out, int out_size) {
    const float* x      = (const float*)d_in[0];
    const float* gate_w = (const float*)d_in[1];
    const float* gate_b = (const float*)d_in[2];
    const float* w1     = (const float*)d_in[3];
    const float* b1     = (const float*)d_in[4];
    const float* w2     = (const float*)d_in[5];
    const float* b2     = (const float*)d_in[6];
    float* out = (float*)d_out;

    zero_counts_kernel<<<1, 32>>>();
    gate_kernel<<<T_TOK / 8, 256>>>(x, gate_w, gate_b);
    scan_kernel<<<1, 32>>>();
    fill_kernel<<<T_TOK / 256, 256>>>();

    dim3 g1(FFN_DIM / BN, (T_TOK + BM - 1) / BM, NEXP);  // (32, 64, 8)
    gemm1_kernel<<<g1, NTHREADS>>>(x, w1, b1);

    dim3 g2(HID / BN, (T_TOK + BM - 1) / BM, NEXP);      // (8, 64, 8)
    gemm2_kernel<<<g2, NTHREADS>>>(w2, b2);

    combine_kernel<<<(T_TOK * HID / 4 + 255) / 256, 256>>>(out);
}